// round 11
// baseline (speedup 1.0000x reference)
#include <cuda_runtime.h>
#include <math.h>

#define BB 128
#define QQ 500
#define NCLS 80
#define TT 64
#define FULL 0xffffffffu

__device__ __forceinline__ unsigned f2ord(float f) {
    unsigned u = __float_as_uint(f);
    return (u & 0x80000000u) ? ~u : (u | 0x80000000u);
}

// ================= Kernel A: cost matrix (R5-proven, full-chip occupancy) =================
#define KA_THREADS 256

__global__ __launch_bounds__(KA_THREADS)
void cost_kernel(const float* __restrict__ logits,   // [B,Q,C]
                 const float* __restrict__ pboxes,   // [B,Q,4]
                 const int*   __restrict__ tids,     // [B,T]
                 const float* __restrict__ tboxes,   // [B,T,4]
                 const float* __restrict__ imgsz,    // [B,4]
                 float*       __restrict__ out)      // [B,Q,T]
{
    __shared__ float4 s_tr[TT];
    __shared__ float4 s_tn[TT];
    __shared__ float  s_ta[TT];
    __shared__ int    s_cls[TT];

    const int b   = blockIdx.y;
    const int tid = threadIdx.x;

    const float inv0 = 1.0f / imgsz[b * 4 + 0];
    const float inv1 = 1.0f / imgsz[b * 4 + 1];
    const float inv2 = 1.0f / imgsz[b * 4 + 2];
    const float inv3 = 1.0f / imgsz[b * 4 + 3];

    if (tid < TT) {
        float4 tb = ((const float4*)tboxes)[b * TT + tid];
        s_tr[tid] = tb;
        s_tn[tid] = make_float4(tb.x * inv0, tb.y * inv1, tb.z * inv2, tb.w * inv3);
        s_ta[tid] = (tb.z - tb.x) * (tb.w - tb.y);
        s_cls[tid] = tids[b * TT + tid];
    }
    __syncthreads();

    const int t = tid & 63;
    const float4 tr = s_tr[t];
    const float4 tn = s_tn[t];
    const float  ta = s_ta[t];
    const int    cl = s_cls[t];

    const float* lg   = logits + (size_t)b * QQ * NCLS;
    float*       Cout = out    + (size_t)b * QQ * TT;

    #pragma unroll
    for (int rep = 0; rep < 8; rep++) {
        int q = blockIdx.x * 32 + rep * 4 + (tid >> 6);
        if (q >= QQ) break;

        float4 pb = ((const float4*)pboxes)[b * QQ + q];
        float bnx = pb.x * inv0, bny = pb.y * inv1;
        float bnz = pb.z * inv2, bnw = pb.w * inv3;
        float pa  = (pb.z - pb.x) * (pb.w - pb.y);

        float x = __ldg(lg + q * NCLS + cl);
        float p = 1.0f / (1.0f + expf(-x));
        float omp = 1.0f - p;
        float pos = 0.25f * omp * omp * (-logf(p + 1e-8f));
        float neg = 0.75f * p * p * (-log1pf(-p + 1e-8f));
        float ccost = pos - neg;

        float l1 = fabsf(bnx - tn.x) + fabsf(bny - tn.y)
                 + fabsf(bnz - tn.z) + fabsf(bnw - tn.w);

        float iwd = fmaxf(fminf(pb.z, tr.z) - fmaxf(pb.x, tr.x), 0.0f);
        float ihd = fmaxf(fminf(pb.w, tr.w) - fmaxf(pb.y, tr.y), 0.0f);
        float inter = iwd * ihd;
        float uni = pa + ta - inter;
        float iou = inter / uni;
        float ewd = fmaxf(fmaxf(pb.z, tr.z) - fminf(pb.x, tr.x), 0.0f);
        float ehd = fmaxf(fmaxf(pb.w, tr.w) - fminf(pb.y, tr.y), 0.0f);
        float enc = ewd * ehd;
        float giou = iou - (enc - uni) / enc;

        Cout[q * TT + t] = 5.0f * l1 + 2.0f * ccost - 2.0f * giou;
    }
}

// ================= Kernel B: assignment (fused stream+mirror+min init, R9 greedy) =================
#define KB_THREADS 512
#define CSTR 513   // column-major stride: bank = (col + q) % 32

// dynamic smem layout (bytes)
#define OFF_CM    0                           // [64][513] float
#define OFF_PART  (TT * CSTR * 4)             // [16][64] u64 partial keys
#define OFF_VAL   (OFF_PART + 16 * TT * 8)    // [64] u32
#define OFF_RAV   (OFF_VAL + TT * 4)          // [64] u32
#define KB_SMEM   (OFF_RAV + TT * 4)

// warp-cooperative exact (value, ravel) min over one smem column (R9-proven)
__device__ __forceinline__ void colscan(const float* __restrict__ Cm, int col,
                                        int lane, unsigned& mv, unsigned& mr) {
    const float* p = Cm + col * CSTR;
    unsigned best = 0xFFFFFFFFu, bq = 0;
    #pragma unroll
    for (int it = 0; it < 16; it++) {
        int q = lane + (it << 5);
        if (q < QQ) {
            unsigned u = f2ord(p[q]);
            if (u < best) { best = u; bq = (unsigned)q; }   // ascending q: min row on tie
        }
    }
    mv = __reduce_min_sync(FULL, best);
    unsigned cr = (best == mv) ? ((bq << 6) | (unsigned)col) : 0xFFFFFFFFu;
    mr = __reduce_min_sync(FULL, cr);
}

__global__ __launch_bounds__(KB_THREADS, 1)
void assign_kernel(const float* __restrict__ C,    // [B,Q,T]
                   float*       __restrict__ out)
{
    extern __shared__ char smraw[];
    float*    Cm     = (float*)   (smraw + OFF_CM);
    unsigned long long* s_part = (unsigned long long*)(smraw + OFF_PART);
    unsigned* s_val  = (unsigned*)(smraw + OFF_VAL);
    unsigned* s_rav  = (unsigned*)(smraw + OFF_RAV);

    const int b = blockIdx.x, tid = threadIdx.x;
    const int lane = tid & 31, wrp = tid >> 5;
    const float* Cg = C + (size_t)b * QQ * TT;

    // ---- fused stream: gmem -> smem mirror + per-(warp,col) running min ----
    {
        const int c0 = 2 * lane, c1 = 2 * lane + 1;
        unsigned long long m0 = ~0ull, m1 = ~0ull;
        #pragma unroll 4
        for (int k = 0; k < 32; k++) {
            int row = wrp + (k << 4);
            if (row >= QQ) break;
            float2 v = ((const float2*)(Cg + row * TT))[lane];   // coalesced 256B/warp
            Cm[c0 * CSTR + row] = v.x;
            Cm[c1 * CSTR + row] = v.y;
            unsigned long long k0 =
                ((unsigned long long)f2ord(v.x) << 15) | (unsigned)((row << 6) | c0);
            unsigned long long k1 =
                ((unsigned long long)f2ord(v.y) << 15) | (unsigned)((row << 6) | c1);
            if (k0 < m0) m0 = k0;
            if (k1 < m1) m1 = k1;
        }
        s_part[wrp * TT + c0] = m0;
        s_part[wrp * TT + c1] = m1;
    }
    __syncthreads();

    // ---- combine 16 partials per column (64 threads, parallel) ----
    if (tid < TT) {
        unsigned long long k = ~0ull;
        #pragma unroll
        for (int s = 0; s < 16; s++) {
            unsigned long long v = s_part[s * TT + tid];
            if (v < k) k = v;
        }
        s_val[tid] = (unsigned)(k >> 15);
        s_rav[tid] = (unsigned)(k & 0x7FFFull);
    }
    __syncthreads();

    if (wrp != 0) return;   // greedy: warp 0 only

    // ---- greedy (R9-proven verbatim) ----
    unsigned v0 = s_val[lane],      r0 = s_rav[lane];        // col = lane
    unsigned v1 = s_val[lane + 32], r1 = s_rav[lane + 32];   // col = lane+32
    const unsigned DEAD = 0xFFFFFFFFu;
    const float FINF = __int_as_float(0x7F800000);

    float* rows_out = out + (size_t)BB * QQ * TT + (size_t)b * TT;
    float* cols_out = rows_out + (size_t)BB * TT;

    #pragma unroll 1
    for (int s = 0; s < TT; s++) {
        unsigned m = __reduce_min_sync(FULL, v0 < v1 ? v0 : v1);
        unsigned cand = 0xFFFFFFFFu;
        if (v0 == m) cand = r0;
        if (v1 == m && r1 < cand) cand = r1;
        unsigned r = __reduce_min_sync(FULL, cand);   // exact (value, ravel) tie-break

        int i = (int)(r >> 6);
        int j = (int)(r & 63u);
        if (lane == 0) { rows_out[s] = (float)i; cols_out[s] = (float)j; }
        if (s == TT - 1) break;

        // kill column j
        if (lane == (j & 31)) { if (j < 32) v0 = DEAD; else v1 = DEAD; }

        // rescan needs computed from register state before poisoning
        bool n0 = (v0 != DEAD) && ((r0 >> 6) == (unsigned)i);
        bool n1 = (v1 != DEAD) && ((r1 >> 6) == (unsigned)i);

        // poison row i in every column -> future scans need no masking
        Cm[lane * CSTR + i] = FINF;
        Cm[(lane + 32) * CSTR + i] = FINF;

        unsigned bal0 = __ballot_sync(FULL, n0);
        unsigned bal1 = __ballot_sync(FULL, n1);
        if (bal0 | bal1) {
            __syncwarp();   // poisons visible before rescans
            while (bal0) {
                int c = __ffs(bal0) - 1; bal0 &= bal0 - 1;
                unsigned mv, mr;
                colscan(Cm, c, lane, mv, mr);
                if (lane == c) { v0 = mv; r0 = mr; }
            }
            while (bal1) {
                int c = __ffs(bal1) - 1; bal1 &= bal1 - 1;
                unsigned mv, mr;
                colscan(Cm, c + 32, lane, mv, mr);
                if (lane == c) { v1 = mv; r1 = mr; }
            }
        }
    }
}

extern "C" void kernel_launch(void* const* d_in, const int* in_sizes, int n_in,
                              void* d_out, int out_size) {
    const float* logits = (const float*)d_in[0];   // [128,500,80]
    const float* pboxes = (const float*)d_in[1];   // [128,500,4]
    const int*   tids   = (const int*)  d_in[2];   // [128,64]
    const float* tboxes = (const float*)d_in[3];   // [128,64,4]
    const float* imgsz  = (const float*)d_in[4];   // [128,4]
    float* out = (float*)d_out;

    dim3 gA((QQ + 31) / 32, BB);
    cost_kernel<<<gA, KA_THREADS>>>(logits, pboxes, tids, tboxes, imgsz, out);

    cudaFuncSetAttribute(assign_kernel,
                         cudaFuncAttributeMaxDynamicSharedMemorySize, KB_SMEM);
    assign_kernel<<<BB, KB_THREADS, KB_SMEM>>>(out, out);
}

// round 12
// speedup vs baseline: 1.0761x; 1.0761x over previous
#include <cuda_runtime.h>
#include <math.h>

#define BB 128
#define QQ 500
#define NCLS 80
#define TT 64
#define NT 1024
#define CSTR 513   // column-major stride: bank = (col + q) % 32 -> conflict-free
#define FULL 0xffffffffu
#define SMEM_SZ (TT * CSTR * 4)   // 131,328 B dynamic (Cm only)
#define DEADK 0xFFFFFFFFu
#define INFBITS 0x7F800000u

__device__ __forceinline__ unsigned f2ord(float f) {
    unsigned u = __float_as_uint(f);
    return (u & 0x80000000u) ? ~u : (u | 0x80000000u);
}

// warp-cooperative exact (value, ravel) min over one smem column (R9-proven)
__device__ __forceinline__ void colscan(const float* __restrict__ Cm, int col,
                                        int lane, unsigned& mv, unsigned& mr) {
    const float* p = Cm + col * CSTR;
    unsigned best = 0xFFFFFFFFu, bq = 0;
    #pragma unroll
    for (int it = 0; it < 16; it++) {
        int q = lane + (it << 5);
        if (q < QQ) {
            unsigned u = f2ord(p[q]);
            if (u < best) { best = u; bq = (unsigned)q; }
        }
    }
    mv = __reduce_min_sync(FULL, best);
    unsigned cr = (best == mv) ? ((bq << 6) | (unsigned)col) : 0xFFFFFFFFu;
    mr = __reduce_min_sync(FULL, cr);
}

// warp-cooperative exact top-2 ((value,ravel) order) over one smem column
__device__ __forceinline__ void colscan2(const float* __restrict__ Cm, int col,
                                         int lane, unsigned& mv, unsigned& mr,
                                         unsigned& bv, unsigned& br) {
    const float* p = Cm + col * CSTR;
    unsigned long long b1 = ~0ull, b2 = ~0ull;
    #pragma unroll
    for (int it = 0; it < 16; it++) {
        int q = lane + (it << 5);
        if (q < QQ) {
            unsigned long long k =
                ((unsigned long long)f2ord(p[q]) << 15) | (unsigned)((q << 6) | col);
            if (k < b1)      { b2 = b1; b1 = k; }
            else if (k < b2) { b2 = k; }
        }
    }
    unsigned lv = (unsigned)(b1 >> 15);
    unsigned m1 = __reduce_min_sync(FULL, lv);
    unsigned c1 = (lv == m1) ? (unsigned)(b1 & 0x7FFFull) : 0xFFFFFFFFu;
    unsigned r1 = __reduce_min_sync(FULL, c1);
    bool own = (lv == m1) && ((unsigned)(b1 & 0x7FFFull) == r1);

    unsigned long long c2k = own ? b2 : b1;   // drop global #1, re-min
    unsigned lv2 = (unsigned)(c2k >> 15);
    unsigned m2 = __reduce_min_sync(FULL, lv2);
    unsigned c2 = (lv2 == m2) ? (unsigned)(c2k & 0x7FFFull) : 0xFFFFFFFFu;
    unsigned r2 = __reduce_min_sync(FULL, c2);

    mv = m1; mr = r1; bv = m2; br = r2;
}

__global__ __launch_bounds__(NT, 1)
void hungarian_fused(const float* __restrict__ logits,   // [B,Q,C]
                     const float* __restrict__ pboxes,   // [B,Q,4]
                     const int*   __restrict__ tids,     // [B,T]
                     const float* __restrict__ tboxes,   // [B,T,4]
                     const float* __restrict__ imgsz,    // [B,4]
                     float*       __restrict__ out)
{
    extern __shared__ float Cm[];           // [64][513]
    __shared__ float4  s_tr[TT];
    __shared__ float4  s_tn[TT];
    __shared__ float   s_ta[TT];
    __shared__ int     s_cls[TT];
    __shared__ unsigned long long s_part[16 * TT];   // per (q-slice, col) partial keys
    __shared__ unsigned s_val[TT], s_rav[TT];

    const int b = blockIdx.x, tid = threadIdx.x;
    const int lane = tid & 31, wrp = tid >> 5;

    const float inv0 = 1.0f / imgsz[b * 4 + 0];
    const float inv1 = 1.0f / imgsz[b * 4 + 1];
    const float inv2 = 1.0f / imgsz[b * 4 + 2];
    const float inv3 = 1.0f / imgsz[b * 4 + 3];

    if (tid < TT) {
        float4 tb = ((const float4*)tboxes)[b * TT + tid];
        s_tr[tid] = tb;
        s_tn[tid] = make_float4(tb.x * inv0, tb.y * inv1, tb.z * inv2, tb.w * inv3);
        s_ta[tid] = (tb.z - tb.x) * (tb.w - tb.y);
        s_cls[tid] = tids[b * TT + tid];
    }
    __syncthreads();

    // ---- Phase 1: cost matrix -> smem + gmem, with fused per-slice column minima ----
    const int t  = tid & 63;
    const int qg = tid >> 6;
    const float4 tr = s_tr[t];
    const float4 tn = s_tn[t];
    const float  ta = s_ta[t];
    const int    cl = s_cls[t];

    const float* lg   = logits + (size_t)b * QQ * NCLS;
    float*       Cout = out    + (size_t)b * QQ * TT;

    unsigned long long mink = ~0ull;

    #pragma unroll 4
    for (int k = 0; k < 32; k++) {
        int q = qg + (k << 4);
        if (q >= QQ) break;

        float4 pb = ((const float4*)pboxes)[b * QQ + q];   // uniform within warp
        float bnx = pb.x * inv0, bny = pb.y * inv1;
        float bnz = pb.z * inv2, bnw = pb.w * inv3;
        float pa  = (pb.z - pb.x) * (pb.w - pb.y);

        float x = __ldg(lg + q * NCLS + cl);
        float p = 1.0f / (1.0f + expf(-x));
        float omp = 1.0f - p;
        float pos = 0.25f * omp * omp * (-logf(p + 1e-8f));
        float neg = 0.75f * p * p * (-log1pf(-p + 1e-8f));
        float ccost = pos - neg;

        float l1 = fabsf(bnx - tn.x) + fabsf(bny - tn.y)
                 + fabsf(bnz - tn.z) + fabsf(bnw - tn.w);

        float iwd = fmaxf(fminf(pb.z, tr.z) - fmaxf(pb.x, tr.x), 0.0f);
        float ihd = fmaxf(fminf(pb.w, tr.w) - fmaxf(pb.y, tr.y), 0.0f);
        float inter = iwd * ihd;
        float uni = pa + ta - inter;
        float iou = inter / uni;
        float ewd = fmaxf(fmaxf(pb.z, tr.z) - fminf(pb.x, tr.x), 0.0f);
        float ehd = fmaxf(fmaxf(pb.w, tr.w) - fminf(pb.y, tr.y), 0.0f);
        float enc = ewd * ehd;
        float giou = iou - (enc - uni) / enc;

        float cost = 5.0f * l1 + 2.0f * ccost - 2.0f * giou;
        Cm[t * CSTR + q] = cost;     // conflict-free
        Cout[q * TT + t] = cost;     // coalesced

        unsigned long long key =
            ((unsigned long long)f2ord(cost) << 15) | (unsigned)((q << 6) | t);
        if (key < mink) mink = key;
    }
    s_part[qg * TT + t] = mink;
    __syncthreads();

    // ---- combine 16 slice-partials per column (64 threads) ----
    if (tid < TT) {
        unsigned long long k = ~0ull;
        #pragma unroll
        for (int s = 0; s < 16; s++) {
            unsigned long long v = s_part[s * TT + tid];
            if (v < k) k = v;
        }
        s_val[tid] = (unsigned)(k >> 15);
        s_rav[tid] = (unsigned)(k & 0x7FFFull);
    }
    __syncthreads();

    if (wrp != 0) return;   // greedy: warp 0 only

    // ---- Phase 3: greedy (R9 step body) + lazily-stocked backups ----
    unsigned v0 = s_val[lane],      r0 = s_rav[lane];        // col = lane
    unsigned v1 = s_val[lane + 32], r1 = s_rav[lane + 32];   // col = lane+32
    unsigned b0v = DEADK, b0r = 0, b1v = DEADK, b1r = 0;     // backups (empty)
    const float FINF = __int_as_float(INFBITS);

    float* rows_out = out + (size_t)BB * QQ * TT + (size_t)b * TT;
    float* cols_out = rows_out + (size_t)BB * TT;

    #pragma unroll 1
    for (int s = 0; s < TT; s++) {
        unsigned m = __reduce_min_sync(FULL, v0 < v1 ? v0 : v1);
        unsigned cand = 0xFFFFFFFFu;
        if (v0 == m) cand = r0;
        if (v1 == m && r1 < cand) cand = r1;
        unsigned r = __reduce_min_sync(FULL, cand);   // exact (value, ravel) tie-break

        int i = (int)(r >> 6);
        int j = (int)(r & 63u);
        if (lane == 0) { rows_out[s] = (float)i; cols_out[s] = (float)j; }
        if (s == TT - 1) break;

        // kill column j
        if (lane == (j & 31)) { if (j < 32) v0 = DEADK; else v1 = DEADK; }

        // which live columns lost their cached row? (register state, pre-poison)
        bool n0 = (v0 != DEADK) && ((r0 >> 6) == (unsigned)i);
        bool n1 = (v1 != DEADK) && ((r1 >> 6) == (unsigned)i);

        // poison row i in every column
        Cm[lane * CSTR + i] = FINF;
        Cm[(lane + 32) * CSTR + i] = FINF;

        unsigned bal0 = __ballot_sync(FULL, n0);
        unsigned bal1 = __ballot_sync(FULL, n1);
        if (bal0 | bal1) {
            __syncwarp();   // poisons visible (also covers backup validation reads)

            // lazy backup promotion: 1 LDS validates the backup's row is alive
            if (n0 && b0v != DEADK) {
                unsigned q2 = b0r >> 6;
                if (__float_as_uint(Cm[lane * CSTR + q2]) != INFBITS) {
                    v0 = b0v; r0 = b0r; n0 = false;
                }
                b0v = DEADK;
            }
            if (n1 && b1v != DEADK) {
                unsigned q2 = b1r >> 6;
                if (__float_as_uint(Cm[(lane + 32) * CSTR + q2]) != INFBITS) {
                    v1 = b1v; r1 = b1r; n1 = false;
                }
                b1v = DEADK;
            }

            bal0 = __ballot_sync(FULL, n0);
            bal1 = __ballot_sync(FULL, n1);
            while (bal0) {
                int c = __ffs(bal0) - 1; bal0 &= bal0 - 1;
                unsigned mv, mr, bv, br;
                colscan2(Cm, c, lane, mv, mr, bv, br);
                if (lane == c) { v0 = mv; r0 = mr; b0v = bv; b0r = br; }
            }
            while (bal1) {
                int c = __ffs(bal1) - 1; bal1 &= bal1 - 1;
                unsigned mv, mr, bv, br;
                colscan2(Cm, c + 32, lane, mv, mr, bv, br);
                if (lane == c) { v1 = mv; r1 = mr; b1v = bv; b1r = br; }
            }
        }
    }
}

extern "C" void kernel_launch(void* const* d_in, const int* in_sizes, int n_in,
                              void* d_out, int out_size) {
    const float* logits = (const float*)d_in[0];   // [128,500,80]
    const float* pboxes = (const float*)d_in[1];   // [128,500,4]
    const int*   tids   = (const int*)  d_in[2];   // [128,64]
    const float* tboxes = (const float*)d_in[3];   // [128,64,4]
    const float* imgsz  = (const float*)d_in[4];   // [128,4]
    float* out = (float*)d_out;

    cudaFuncSetAttribute(hungarian_fused,
                         cudaFuncAttributeMaxDynamicSharedMemorySize, SMEM_SZ);
    hungarian_fused<<<BB, NT, SMEM_SZ>>>(logits, pboxes, tids, tboxes, imgsz, out);
}

// round 13
// speedup vs baseline: 1.1655x; 1.0831x over previous
#include <cuda_runtime.h>
#include <math.h>

#define BB 128
#define QQ 500
#define NCLS 80
#define TT 64
#define NT 1024
#define CSTR 513   // column-major stride: bank = (col + q) % 32 -> conflict-free
#define FULL 0xffffffffu
#define SMEM_SZ (TT * CSTR * 4)   // 131,328 B dynamic (Cm only)
#define DEADK 0xFFFFFFFFu

__device__ __forceinline__ unsigned f2ord(float f) {
    unsigned u = __float_as_uint(f);
    return (u & 0x80000000u) ? ~u : (u | 0x80000000u);
}

// warp-cooperative exact (value, ravel) min over one smem column (R9-proven)
__device__ __forceinline__ void colscan(const float* __restrict__ Cm, int col,
                                        int lane, unsigned& mv, unsigned& mr) {
    const float* p = Cm + col * CSTR;
    unsigned best = 0xFFFFFFFFu, bq = 0;
    #pragma unroll
    for (int it = 0; it < 16; it++) {
        int q = lane + (it << 5);
        if (q < QQ) {
            unsigned u = f2ord(p[q]);
            if (u < best) { best = u; bq = (unsigned)q; }
        }
    }
    mv = __reduce_min_sync(FULL, best);
    unsigned cr = (best == mv) ? ((bq << 6) | (unsigned)col) : 0xFFFFFFFFu;
    mr = __reduce_min_sync(FULL, cr);
}

// one cost element; bit-identical ops to all passing rounds
__device__ __forceinline__ float cost_elem(float4 pb, float4 bn, float pa, float x,
                                           float4 tr, float4 tn, float ta) {
    float p = 1.0f / (1.0f + expf(-x));
    float omp = 1.0f - p;
    float pos = 0.25f * omp * omp * (-logf(p + 1e-8f));
    float neg = 0.75f * p * p * (-log1pf(-p + 1e-8f));
    float ccost = pos - neg;

    float l1 = fabsf(bn.x - tn.x) + fabsf(bn.y - tn.y)
             + fabsf(bn.z - tn.z) + fabsf(bn.w - tn.w);

    float iwd = fmaxf(fminf(pb.z, tr.z) - fmaxf(pb.x, tr.x), 0.0f);
    float ihd = fmaxf(fminf(pb.w, tr.w) - fmaxf(pb.y, tr.y), 0.0f);
    float inter = iwd * ihd;
    float uni = pa + ta - inter;
    float iou = inter / uni;
    float ewd = fmaxf(fmaxf(pb.z, tr.z) - fminf(pb.x, tr.x), 0.0f);
    float ehd = fmaxf(fmaxf(pb.w, tr.w) - fminf(pb.y, tr.y), 0.0f);
    float enc = ewd * ehd;
    float giou = iou - (enc - uni) / enc;

    return 5.0f * l1 + 2.0f * ccost - 2.0f * giou;
}

__global__ __launch_bounds__(NT, 1)
void hungarian_fused(const float* __restrict__ logits,   // [B,Q,C]
                     const float* __restrict__ pboxes,   // [B,Q,4]
                     const int*   __restrict__ tids,     // [B,T]
                     const float* __restrict__ tboxes,   // [B,T,4]
                     const float* __restrict__ imgsz,    // [B,4]
                     float*       __restrict__ out)
{
    extern __shared__ float Cm[];           // [64][513]
    __shared__ float4  s_tr[TT];
    __shared__ float4  s_tn[TT];
    __shared__ float   s_ta[TT];
    __shared__ int     s_cls[TT];
    __shared__ float4  s_pr[QQ];            // raw pred boxes
    __shared__ float4  s_bn[QQ];            // normalized pred boxes
    __shared__ float   s_pa[QQ];            // pred areas
    __shared__ unsigned s_val[TT], s_rav[TT];

    const int b = blockIdx.x, tid = threadIdx.x;
    const int lane = tid & 31, wrp = tid >> 5;

    const float inv0 = 1.0f / imgsz[b * 4 + 0];
    const float inv1 = 1.0f / imgsz[b * 4 + 1];
    const float inv2 = 1.0f / imgsz[b * 4 + 2];
    const float inv3 = 1.0f / imgsz[b * 4 + 3];

    if (tid < TT) {
        float4 tb = ((const float4*)tboxes)[b * TT + tid];
        s_tr[tid] = tb;
        s_tn[tid] = make_float4(tb.x * inv0, tb.y * inv1, tb.z * inv2, tb.w * inv3);
        s_ta[tid] = (tb.z - tb.x) * (tb.w - tb.y);
        s_cls[tid] = tids[b * TT + tid];
    }
    if (tid < QQ) {
        float4 pb = ((const float4*)pboxes)[b * QQ + tid];
        s_pr[tid] = pb;
        s_bn[tid] = make_float4(pb.x * inv0, pb.y * inv1, pb.z * inv2, pb.w * inv3);
        s_pa[tid] = (pb.z - pb.x) * (pb.w - pb.y);
    }
    __syncthreads();

    // ---- Phase 1: cost matrix, 2 independent q-chains per iteration ----
    const int t  = tid & 63;
    const int qg = tid >> 6;                 // 0..15
    const float4 tr = s_tr[t];
    const float4 tn = s_tn[t];
    const float  ta = s_ta[t];
    const int    cl = s_cls[t];

    const float* lg   = logits + (size_t)b * QQ * NCLS;
    float*       Cout = out    + (size_t)b * QQ * TT;

    #pragma unroll 1
    for (int k2 = 0; k2 < 15; k2++) {
        int qa = qg + (k2 << 5);             // qg + 32k <= 495: always valid
        int qb = qa + 16;
        float xA = __ldg(lg + qa * NCLS + cl);
        float xB = __ldg(lg + qb * NCLS + cl);
        float cA = cost_elem(s_pr[qa], s_bn[qa], s_pa[qa], xA, tr, tn, ta);
        float cB = cost_elem(s_pr[qb], s_bn[qb], s_pa[qb], xB, tr, tn, ta);
        Cm[t * CSTR + qa] = cA;
        Cout[qa * TT + t] = cA;
        Cm[t * CSTR + qb] = cB;
        Cout[qb * TT + t] = cB;
    }
    {   // tail: qa = qg+480 always valid; qb = qg+496 valid only for qg < 4
        int qa = qg + 480;
        float xA = __ldg(lg + qa * NCLS + cl);
        float cA = cost_elem(s_pr[qa], s_bn[qa], s_pa[qa], xA, tr, tn, ta);
        Cm[t * CSTR + qa] = cA;
        Cout[qa * TT + t] = cA;
        if (qg < 4) {
            int qb = qa + 16;
            float xB = __ldg(lg + qb * NCLS + cl);
            float cB = cost_elem(s_pr[qb], s_bn[qb], s_pa[qb], xB, tr, tn, ta);
            Cm[t * CSTR + qb] = cB;
            Cout[qb * TT + t] = cB;
        }
    }
    __syncthreads();

    // ---- Phase 2: initial per-column (value, ravel) keys (R9) ----
    {
        unsigned mv, mr;
        colscan(Cm, wrp, lane, mv, mr);
        if (lane == 0) { s_val[wrp] = mv; s_rav[wrp] = mr; }
        colscan(Cm, wrp + 32, lane, mv, mr);
        if (lane == 0) { s_val[wrp + 32] = mv; s_rav[wrp + 32] = mr; }
    }
    __syncthreads();

    if (wrp != 0) return;   // greedy: warp 0 only

    // ---- Phase 3: greedy (R9-proven verbatim) ----
    unsigned v0 = s_val[lane],      r0 = s_rav[lane];        // col = lane
    unsigned v1 = s_val[lane + 32], r1 = s_rav[lane + 32];   // col = lane+32
    const float FINF = __int_as_float(0x7F800000);

    float* rows_out = out + (size_t)BB * QQ * TT + (size_t)b * TT;
    float* cols_out = rows_out + (size_t)BB * TT;

    #pragma unroll 1
    for (int s = 0; s < TT; s++) {
        unsigned m = __reduce_min_sync(FULL, v0 < v1 ? v0 : v1);
        unsigned cand = 0xFFFFFFFFu;
        if (v0 == m) cand = r0;
        if (v1 == m && r1 < cand) cand = r1;
        unsigned r = __reduce_min_sync(FULL, cand);   // exact (value, ravel) tie-break

        int i = (int)(r >> 6);
        int j = (int)(r & 63u);
        if (lane == 0) { rows_out[s] = (float)i; cols_out[s] = (float)j; }
        if (s == TT - 1) break;

        // kill column j
        if (lane == (j & 31)) { if (j < 32) v0 = DEADK; else v1 = DEADK; }

        // rescan needs from register state before poisoning
        bool n0 = (v0 != DEADK) && ((r0 >> 6) == (unsigned)i);
        bool n1 = (v1 != DEADK) && ((r1 >> 6) == (unsigned)i);

        // poison row i in every column -> future scans maskless
        Cm[lane * CSTR + i] = FINF;
        Cm[(lane + 32) * CSTR + i] = FINF;

        unsigned bal0 = __ballot_sync(FULL, n0);
        unsigned bal1 = __ballot_sync(FULL, n1);
        if (bal0 | bal1) {
            __syncwarp();   // poisons visible before rescans
            while (bal0) {
                int c = __ffs(bal0) - 1; bal0 &= bal0 - 1;
                unsigned mv, mr;
                colscan(Cm, c, lane, mv, mr);
                if (lane == c) { v0 = mv; r0 = mr; }
            }
            while (bal1) {
                int c = __ffs(bal1) - 1; bal1 &= bal1 - 1;
                unsigned mv, mr;
                colscan(Cm, c + 32, lane, mv, mr);
                if (lane == c) { v1 = mv; r1 = mr; }
            }
        }
    }
}

extern "C" void kernel_launch(void* const* d_in, const int* in_sizes, int n_in,
                              void* d_out, int out_size) {
    const float* logits = (const float*)d_in[0];   // [128,500,80]
    const float* pboxes = (const float*)d_in[1];   // [128,500,4]
    const int*   tids   = (const int*)  d_in[2];   // [128,64]
    const float* tboxes = (const float*)d_in[3];   // [128,64,4]
    const float* imgsz  = (const float*)d_in[4];   // [128,4]
    float* out = (float*)d_out;

    cudaFuncSetAttribute(hungarian_fused,
                         cudaFuncAttributeMaxDynamicSharedMemorySize, SMEM_SZ);
    hungarian_fused<<<BB, NT, SMEM_SZ>>>(logits, pboxes, tids, tboxes, imgsz, out);
}